// round 5
// baseline (speedup 1.0000x reference)
#include <cuda_runtime.h>
#include <math.h>

// ---------------------------------------------------------------------------
// Problem constants: B=128, T=1024, D=512, H=512, 4H=2048
// Inputs (metadata order):
//   0: sequence_tensor f32 [128,1024,512]
//   1: batch_lengths   int32 OR int64 [128]  (JAX x64-disabled -> int32!)
//   2: W_ih            f32 [2048,512]
//   3: W_hh            f32 [2048,512]
//   4: b_ih            f32 [2048]
//   5: b_hh            f32 [2048]
// Output: concat( out[128,1024,512], h_final[1,128,512], c_final[1,128,512] )
// ---------------------------------------------------------------------------

#define Bsz   128
#define Tsz   1024
#define Dsz   512
#define Hsz   512
#define G4    2048

// Scratch: precomputed input gates  G[t][b][j], j in [0,2048)  (1 GiB)
__device__ float g_G[(size_t)Tsz * Bsz * G4];
// Double-buffered hidden state h[b][k]
__device__ float g_hbuf[2][Bsz * Hsz];
// Canonical int lengths (dtype-normalized)
__device__ int g_len[Bsz];
// Software grid barrier state
__device__ unsigned g_bar_cnt;
__device__ volatile unsigned g_bar_gen;

// ---------------------------------------------------------------------------
// Length dtype normalization.  Reference does astype(jnp.int64) but JAX with
// x64 disabled (default) yields int32.  Detect: int64 values < 2^31 have zero
// high words at odd int32 slots; int32 lengths are always >= 1.
// ---------------------------------------------------------------------------
__global__ void convert_lens_kernel(const void* lensraw)
{
    const int* p = (const int*)lensraw;
    __shared__ int is64;
    if (threadIdx.x == 0)
        is64 = (p[1] == 0 && p[3] == 0 && p[5] == 0) ? 1 : 0;
    __syncthreads();
    const int b = threadIdx.x;                       // 0..127
    g_len[b] = is64 ? p[b * 2] : p[b];
}

// ---------------------------------------------------------------------------
// Phase 1: G[t][b][j] = sum_k seq[b][t][k] * W_ih[j][k] + (b_ih[j] + b_hh[j])
// Classic 128x128x16 SGEMM.  A 128-row M tile = one timestep t, all 128 batch
// rows (lengths sorted desc -> skip FMAs for fully-inactive 8-row groups).
// ---------------------------------------------------------------------------
__global__ void __launch_bounds__(256) pregemm_kernel(
    const float* __restrict__ seq,
    const float* __restrict__ Wih,
    const float* __restrict__ bih,
    const float* __restrict__ bhh)
{
    __shared__ float As[16][128];
    __shared__ float Bs[16][128];

    const int t   = blockIdx.y;          // timestep
    const int j0  = blockIdx.x * 128;    // gate-column tile
    const int tid = threadIdx.x;
    const int tx  = tid & 15;            // 16 col-groups of 8
    const int ty  = tid >> 4;            // 16 row-groups of 8

    // rows ty*8 .. ty*8+7; lens sorted desc -> group active iff first row is.
    const bool grpActive = (g_len[ty * 8] > t);

    float acc[8][8];
#pragma unroll
    for (int j = 0; j < 8; ++j) {
        const float bv = bih[j0 + tx * 8 + j] + bhh[j0 + tx * 8 + j];
#pragma unroll
        for (int i = 0; i < 8; ++i) acc[i][j] = bv;
    }

    const int lm = tid >> 1;            // 0..127
    const int lk = (tid & 1) * 8;       // 0 or 8
    const float* arow = seq + ((size_t)lm * Tsz + t) * Dsz + lk;
    const float* brow = Wih + (size_t)(j0 + lm) * Dsz + lk;

    for (int k0 = 0; k0 < Dsz; k0 += 16) {
        const float4 av0 = *(const float4*)(arow + k0);
        const float4 av1 = *(const float4*)(arow + k0 + 4);
        const float4 bv0 = *(const float4*)(brow + k0);
        const float4 bv1 = *(const float4*)(brow + k0 + 4);
        As[lk + 0][lm] = av0.x; As[lk + 1][lm] = av0.y;
        As[lk + 2][lm] = av0.z; As[lk + 3][lm] = av0.w;
        As[lk + 4][lm] = av1.x; As[lk + 5][lm] = av1.y;
        As[lk + 6][lm] = av1.z; As[lk + 7][lm] = av1.w;
        Bs[lk + 0][lm] = bv0.x; Bs[lk + 1][lm] = bv0.y;
        Bs[lk + 2][lm] = bv0.z; Bs[lk + 3][lm] = bv0.w;
        Bs[lk + 4][lm] = bv1.x; Bs[lk + 5][lm] = bv1.y;
        Bs[lk + 6][lm] = bv1.z; Bs[lk + 7][lm] = bv1.w;
        __syncthreads();

        if (grpActive) {
#pragma unroll
            for (int kk = 0; kk < 16; ++kk) {
                const float4 a0 = *(const float4*)&As[kk][ty * 8];
                const float4 a1 = *(const float4*)&As[kk][ty * 8 + 4];
                const float4 b0 = *(const float4*)&Bs[kk][tx * 8];
                const float4 b1 = *(const float4*)&Bs[kk][tx * 8 + 4];
                const float a[8] = {a0.x, a0.y, a0.z, a0.w, a1.x, a1.y, a1.z, a1.w};
                const float b[8] = {b0.x, b0.y, b0.z, b0.w, b1.x, b1.y, b1.z, b1.w};
#pragma unroll
                for (int i = 0; i < 8; ++i)
#pragma unroll
                    for (int j = 0; j < 8; ++j)
                        acc[i][j] += a[i] * b[j];
            }
        }
        __syncthreads();
    }

    if (grpActive) {
#pragma unroll
        for (int i = 0; i < 8; ++i) {
            const size_t o = ((size_t)t * Bsz + ty * 8 + i) * G4 + j0 + tx * 8;
            *(float4*)&g_G[o]     = make_float4(acc[i][0], acc[i][1], acc[i][2], acc[i][3]);
            *(float4*)&g_G[o + 4] = make_float4(acc[i][4], acc[i][5], acc[i][6], acc[i][7]);
        }
    }
}

// ---------------------------------------------------------------------------
// Software grid barrier (128 blocks, all resident: 1 block/SM, 152 SMs).
// Release: all threads __threadfence() before arrival.  Acquire: all threads
// __threadfence() after release observed (CCTL.IVALL -> L1D flush on sm_103a).
// ---------------------------------------------------------------------------
__device__ __forceinline__ void grid_barrier(unsigned nblocks)
{
    __threadfence();                         // release: all threads
    __syncthreads();
    if (threadIdx.x == 0) {
        const unsigned old = g_bar_gen;      // read gen BEFORE arriving
        const unsigned ticket = atomicAdd(&g_bar_cnt, 1u);
        if (ticket == nblocks - 1u) {
            g_bar_cnt = 0;
            __threadfence();
            g_bar_gen = old + 1u;            // release the barrier
        } else {
            while (g_bar_gen == old) { }     // spin (volatile)
        }
    }
    __syncthreads();
    __threadfence();                         // acquire: all threads
}

__device__ __forceinline__ float sigmf(float x) { return 1.f / (1.f + expf(-x)); }

// ---------------------------------------------------------------------------
// Phase 2: persistent recurrence kernel.
// 128 blocks: block = (btile 0..3 [32 batch rows]) x (ntile 0..31 [16 hidden]).
// Tile column c = 4*n_off + gate -> each thread's 4 columns are the 4 gates of
// ONE hidden unit, so the LSTM update is thread-local.  W_hh tile (64x512,
// 128KB) staged in smem once; h staged per step from double-buffered global;
// c state in registers.
// ---------------------------------------------------------------------------
__global__ void __launch_bounds__(256) lstm_steps_kernel(
    const float* __restrict__ Whh,
    float* __restrict__ out,    // [B,T,H]
    float* __restrict__ hfin,   // [B,H]
    float* __restrict__ cfin)   // [B,H]
{
    extern __shared__ float sm[];
    float* W_s = sm;                 // [512][64]  W_s[k][c]
    float* h_s = sm + 512 * 64;      // [512][32]  h_s[k][b_local]

    const int tid   = threadIdx.x;
    const int bx    = blockIdx.x;        // 0..127
    const int ntile = bx & 31;
    const int btile = bx >> 5;
    const int n0    = ntile * 16;
    const int b0    = btile * 32;

    // ---- stage W_hh tile (once): W_s[k][c] = Whh[(c&3)*512 + n0 + (c>>2)][k]
    {
        const int c = tid >> 2;                       // 0..63
        const int j = (c & 3) * Hsz + n0 + (c >> 2);  // W_hh row
        const float* wrow = Whh + (size_t)j * Hsz;
        for (int k = (tid & 3) * 4; k < Hsz; k += 16) {
            const float4 v = *(const float4*)(wrow + k);
            W_s[(k + 0) * 64 + c] = v.x;
            W_s[(k + 1) * 64 + c] = v.y;
            W_s[(k + 2) * 64 + c] = v.z;
            W_s[(k + 3) * 64 + c] = v.w;
        }
    }
    // ---- zero this block's slice of hbuf[0]
#pragma unroll
    for (int q = 0; q < 2; ++q) {
        const int idx = tid + q * 256;                // 0..511
        const int r = idx >> 4, cc = idx & 15;
        g_hbuf[0][(size_t)(b0 + r) * Hsz + n0 + cc] = 0.f;
    }
    grid_barrier(128);

    const int my = tid >> 4;            // 0..15 -> rows b_r0, b_r0+1
    const int nx = tid & 15;            // 0..15 -> hidden unit n
    const int b_r0 = b0 + my * 2;
    const int n    = n0 + nx;
    const int len_tile = g_len[b0];
    const int len0 = g_len[b_r0];
    const int len1 = g_len[b_r0 + 1];

    float hprev0 = 0.f, hprev1 = 0.f;   // frozen-capable h state
    float creg0  = 0.f, creg1  = 0.f;   // c state (registers)

    const float* wp = W_s + nx * 4;
    const float* hp = h_s + my * 2;

#pragma unroll 1
    for (int t = 0; t < Tsz; ++t) {
        float* hnext = g_hbuf[(t + 1) & 1];
        const bool tileActive = (t < len_tile);

        if (tileActive) {
            // -- stage h tile [32 rows][512 k] into smem, k-major
            {
                const float* hbuf = g_hbuf[t & 1];
                const int bloc = tid & 31;
                const int kblk = tid >> 5;
                const float* hb = hbuf + (size_t)(b0 + bloc) * Hsz + kblk * 64;
#pragma unroll
                for (int i = 0; i < 16; ++i) {
                    const float4 v = *(const float4*)(hb + i * 4);
                    const int k = kblk * 64 + i * 4;
                    h_s[(k + 0) * 32 + bloc] = v.x;
                    h_s[(k + 1) * 32 + bloc] = v.y;
                    h_s[(k + 2) * 32 + bloc] = v.z;
                    h_s[(k + 3) * 32 + bloc] = v.w;
                }
            }
            __syncthreads();

            // -- 2x4 micro-GEMM over K=512
            float a0x = 0.f, a0y = 0.f, a0z = 0.f, a0w = 0.f;
            float a1x = 0.f, a1y = 0.f, a1z = 0.f, a1w = 0.f;
#pragma unroll 8
            for (int k = 0; k < Hsz; ++k) {
                const float4 w  = *(const float4*)(wp + k * 64);
                const float2 h2 = *(const float2*)(hp + k * 32);
                a0x += h2.x * w.x; a0y += h2.x * w.y;
                a0z += h2.x * w.z; a0w += h2.x * w.w;
                a1x += h2.y * w.x; a1y += h2.y * w.y;
                a1z += h2.y * w.z; a1w += h2.y * w.w;
            }

            // -- elementwise LSTM update for 2 batch rows
            const float* Gt = g_G + (size_t)t * Bsz * G4;
            {
                const float* gr = Gt + (size_t)b_r0 * G4 + n;
                const float iv = sigmf(a0x + gr[0]);
                const float fv = sigmf(a0y + gr[512]);
                const float gv = tanhf(a0z + gr[1024]);
                const float ov = sigmf(a0w + gr[1536]);
                const float cn = fv * creg0 + iv * gv;
                const float hn = ov * tanhf(cn);
                const bool act = (t < len0);
                creg0  = act ? cn : creg0;
                hprev0 = act ? hn : hprev0;
                out[((size_t)b_r0 * Tsz + t) * Hsz + n] = act ? hn : 0.f;
                hnext[(size_t)b_r0 * Hsz + n] = hprev0;
            }
            {
                const float* gr = Gt + (size_t)(b_r0 + 1) * G4 + n;
                const float iv = sigmf(a1x + gr[0]);
                const float fv = sigmf(a1y + gr[512]);
                const float gv = tanhf(a1z + gr[1024]);
                const float ov = sigmf(a1w + gr[1536]);
                const float cn = fv * creg1 + iv * gv;
                const float hn = ov * tanhf(cn);
                const bool act = (t < len1);
                creg1  = act ? cn : creg1;
                hprev1 = act ? hn : hprev1;
                out[((size_t)(b_r0 + 1) * Tsz + t) * Hsz + n] = act ? hn : 0.f;
                hnext[(size_t)(b_r0 + 1) * Hsz + n] = hprev1;
            }
        } else {
            // whole batch tile inactive: zero outputs, carry h forward
            out[((size_t)b_r0 * Tsz + t) * Hsz + n]       = 0.f;
            out[((size_t)(b_r0 + 1) * Tsz + t) * Hsz + n] = 0.f;
            hnext[(size_t)b_r0 * Hsz + n]       = hprev0;
            hnext[(size_t)(b_r0 + 1) * Hsz + n] = hprev1;
        }

        grid_barrier(128);   // h double-buffer handoff for step t+1
    }

    // final (frozen) states
    hfin[(size_t)b_r0 * Hsz + n]       = hprev0;
    hfin[(size_t)(b_r0 + 1) * Hsz + n] = hprev1;
    cfin[(size_t)b_r0 * Hsz + n]       = creg0;
    cfin[(size_t)(b_r0 + 1) * Hsz + n] = creg1;
}

// ---------------------------------------------------------------------------
extern "C" void kernel_launch(void* const* d_in, const int* in_sizes, int n_in,
                              void* d_out, int out_size)
{
    (void)in_sizes; (void)n_in; (void)out_size;
    const float* seq  = (const float*)d_in[0];
    const void*  lens = d_in[1];
    const float* Wih  = (const float*)d_in[2];
    const float* Whh  = (const float*)d_in[3];
    const float* bih  = (const float*)d_in[4];
    const float* bhh  = (const float*)d_in[5];

    float* outp = (float*)d_out;
    float* hfin = outp + (size_t)Bsz * Tsz * Hsz;
    float* cfin = hfin + (size_t)Bsz * Hsz;

    // Opt-in to 192 KB dynamic smem for the persistent kernel (W 128KB + h 64KB)
    cudaFuncSetAttribute(lstm_steps_kernel,
                         cudaFuncAttributeMaxDynamicSharedMemorySize, 196608);

    // Phase 0: normalize length dtype (int32 vs int64)
    convert_lens_kernel<<<1, 128>>>(lens);

    // Phase 1: input-gate GEMM  (16 column tiles x 1024 timesteps)
    dim3 grid1(G4 / 128, Tsz);
    pregemm_kernel<<<grid1, 256>>>(seq, Wih, bih, bhh);

    // Phase 2: persistent recurrence (128 co-resident blocks, sw grid barrier)
    lstm_steps_kernel<<<128, 256, 196608>>>(Whh, outp, hfin, cfin);
}

// round 6
// speedup vs baseline: 1.1220x; 1.1220x over previous
#include <cuda_runtime.h>
#include <math.h>

// ---------------------------------------------------------------------------
// Problem constants: B=128, T=1024, D=512, H=512, 4H=2048
// Inputs (metadata order):
//   0: sequence_tensor f32 [128,1024,512]
//   1: batch_lengths   int32 (JAX x64 off) or int64 [128], sorted descending
//   2: W_ih f32 [2048,512]   3: W_hh f32 [2048,512]
//   4: b_ih f32 [2048]       5: b_hh f32 [2048]
// Output: concat( out[128,1024,512], h_final[1,128,512], c_final[1,128,512] )
// ---------------------------------------------------------------------------

#define Bsz   128
#define Tsz   1024
#define Dsz   512
#define Hsz   512
#define G4    2048

// Scratch: precomputed input gates  G[t][b][j]  (1 GiB)
__device__ float g_G[(size_t)Tsz * Bsz * G4];
// Double-buffered hidden state h[b][k]
__device__ float g_hbuf[2][Bsz * Hsz];
// Software grid barrier state
__device__ unsigned g_bar_cnt;
__device__ volatile unsigned g_bar_gen;

// ---- packed fp32 helpers (FFMA2 path: PTX fma.rn.f32x2) --------------------
__device__ __forceinline__ unsigned long long pack2(float x, float y) {
    unsigned long long r;
    asm("mov.b64 %0, {%1, %2};" : "=l"(r) : "f"(x), "f"(y));
    return r;
}
__device__ __forceinline__ void unpack2(unsigned long long v, float& x, float& y) {
    asm("mov.b64 {%0, %1}, %2;" : "=f"(x), "=f"(y) : "l"(v));
}
#define FMA2(d, a, b) asm("fma.rn.f32x2 %0, %1, %2, %0;" : "+l"(d) : "l"(a), "l"(b))

// ---- length dtype detection (int32 vs int64) --------------------------------
// int64 lengths (<2^31) have zero high words at odd int32 slots; int32
// lengths are always >= 1.
__device__ __forceinline__ bool lens_is64(const int* p) {
    return (p[1] == 0 && p[3] == 0 && p[5] == 0);
}
__device__ __forceinline__ int load_len(const int* p, bool is64, int b) {
    return is64 ? p[2 * b] : p[b];
}

// ---------------------------------------------------------------------------
// Phase 1: G[t][b][j] = sum_k seq[b][t][k] * W_ih[j][k] + (b_ih[j] + b_hh[j])
// 128x128x16 SGEMM per block; inner product in packed f32x2 (FFMA2).
// A 128-row M tile = one timestep t with all 128 batch rows; lengths sorted
// desc -> skip FMAs for fully-inactive 8-row groups.
// ---------------------------------------------------------------------------
__global__ void __launch_bounds__(256) pregemm_kernel(
    const float* __restrict__ seq,
    const float* __restrict__ Wih,
    const float* __restrict__ bih,
    const float* __restrict__ bhh,
    const int*   __restrict__ lensraw)
{
    __shared__ float As[16][128];
    __shared__ float Bs[16][128];

    const int t   = blockIdx.y;          // timestep
    const int j0  = blockIdx.x * 128;    // gate-column tile
    const int tid = threadIdx.x;
    const int tx  = tid & 15;            // 16 col-groups of 8
    const int ty  = tid >> 4;            // 16 row-groups of 8

    const bool is64 = lens_is64(lensraw);
    const bool grpActive = (load_len(lensraw, is64, ty * 8) > t);

    // acc2[i][p]: packed pair (j = 2p, 2p+1) for output row i
    unsigned long long acc2[8][4];
#pragma unroll
    for (int p = 0; p < 4; ++p) {
        const int j = j0 + tx * 8 + 2 * p;
        const unsigned long long bv =
            pack2(bih[j] + bhh[j], bih[j + 1] + bhh[j + 1]);
#pragma unroll
        for (int i = 0; i < 8; ++i) acc2[i][p] = bv;
    }

    const int lm = tid >> 1;            // 0..127
    const int lk = (tid & 1) * 8;       // 0 or 8
    const float* arow = seq + ((size_t)lm * Tsz + t) * Dsz + lk;
    const float* brow = Wih + (size_t)(j0 + lm) * Dsz + lk;

    for (int k0 = 0; k0 < Dsz; k0 += 16) {
        const float4 av0 = *(const float4*)(arow + k0);
        const float4 av1 = *(const float4*)(arow + k0 + 4);
        const float4 bv0 = *(const float4*)(brow + k0);
        const float4 bv1 = *(const float4*)(brow + k0 + 4);
        As[lk + 0][lm] = av0.x; As[lk + 1][lm] = av0.y;
        As[lk + 2][lm] = av0.z; As[lk + 3][lm] = av0.w;
        As[lk + 4][lm] = av1.x; As[lk + 5][lm] = av1.y;
        As[lk + 6][lm] = av1.z; As[lk + 7][lm] = av1.w;
        Bs[lk + 0][lm] = bv0.x; Bs[lk + 1][lm] = bv0.y;
        Bs[lk + 2][lm] = bv0.z; Bs[lk + 3][lm] = bv0.w;
        Bs[lk + 4][lm] = bv1.x; Bs[lk + 5][lm] = bv1.y;
        Bs[lk + 6][lm] = bv1.z; Bs[lk + 7][lm] = bv1.w;
        __syncthreads();

        if (grpActive) {
#pragma unroll
            for (int kk = 0; kk < 16; ++kk) {
                const float4 a0 = *(const float4*)&As[kk][ty * 8];
                const float4 a1 = *(const float4*)&As[kk][ty * 8 + 4];
                // b pairs straight from shared (consecutive floats)
                const ulonglong2 bb0 = *(const ulonglong2*)&Bs[kk][tx * 8];
                const ulonglong2 bb1 = *(const ulonglong2*)&Bs[kk][tx * 8 + 4];
                const float a[8] = {a0.x, a0.y, a0.z, a0.w,
                                    a1.x, a1.y, a1.z, a1.w};
#pragma unroll
                for (int i = 0; i < 8; ++i) {
                    const unsigned long long ad = pack2(a[i], a[i]);
                    FMA2(acc2[i][0], ad, bb0.x);
                    FMA2(acc2[i][1], ad, bb0.y);
                    FMA2(acc2[i][2], ad, bb1.x);
                    FMA2(acc2[i][3], ad, bb1.y);
                }
            }
        }
        __syncthreads();
    }

    if (grpActive) {
#pragma unroll
        for (int i = 0; i < 8; ++i) {
            float f0, f1, f2, f3, f4, f5, f6, f7;
            unpack2(acc2[i][0], f0, f1);
            unpack2(acc2[i][1], f2, f3);
            unpack2(acc2[i][2], f4, f5);
            unpack2(acc2[i][3], f6, f7);
            const size_t o = ((size_t)t * Bsz + ty * 8 + i) * G4 + j0 + tx * 8;
            *(float4*)&g_G[o]     = make_float4(f0, f1, f2, f3);
            *(float4*)&g_G[o + 4] = make_float4(f4, f5, f6, f7);
        }
    }
}

// ---------------------------------------------------------------------------
// Software grid barrier (128 blocks, all resident: 1 block/SM).
// Release: all threads __threadfence() before arrival (stores -> L2 visible
// before flag).  NO acquire fence: all cross-step global reads use __ldcg
// (L2-coherent, bypasses non-coherent L1), so no L1 flush is needed.
// ---------------------------------------------------------------------------
__device__ __forceinline__ void grid_barrier(unsigned nblocks)
{
    __threadfence();                         // release: all threads
    __syncthreads();
    if (threadIdx.x == 0) {
        const unsigned old = g_bar_gen;      // read gen BEFORE arriving
        const unsigned ticket = atomicAdd(&g_bar_cnt, 1u);
        if (ticket == nblocks - 1u) {
            g_bar_cnt = 0;
            __threadfence();
            g_bar_gen = old + 1u;            // release the barrier
        } else {
            while (g_bar_gen == old) { }     // spin (volatile, L2)
        }
    }
    __syncthreads();
}

__device__ __forceinline__ float sigmf(float x) { return 1.f / (1.f + expf(-x)); }

// ---------------------------------------------------------------------------
// Phase 2: persistent recurrence kernel.
// 128 blocks: block = (btile 0..3 [32 batch rows]) x (ntile 0..31 [16 hidden]).
// Tile column c = 4*n_off + gate -> each thread's 4 columns are the 4 gates of
// ONE hidden unit (thread-local LSTM update).  W_hh tile (64x512, 128KB) in
// smem once; h staged per step from double-buffered global (via __ldcg);
// c state in registers.  Micro-GEMM in packed f32x2 (FFMA2).
// ---------------------------------------------------------------------------
__global__ void __launch_bounds__(256) lstm_steps_kernel(
    const float* __restrict__ Whh,
    const int*   __restrict__ lensraw,
    float* __restrict__ out,    // [B,T,H]
    float* __restrict__ hfin,   // [B,H]
    float* __restrict__ cfin)   // [B,H]
{
    extern __shared__ float sm[];
    float* W_s = sm;                 // [512][64]  W_s[k][c]
    float* h_s = sm + 512 * 64;      // [512][32]  h_s[k][b_local]

    const int tid   = threadIdx.x;
    const int bx    = blockIdx.x;        // 0..127
    const int ntile = bx & 31;
    const int btile = bx >> 5;
    const int n0    = ntile * 16;
    const int b0    = btile * 32;

    // ---- stage W_hh tile (once): W_s[k][c] = Whh[(c&3)*512 + n0 + (c>>2)][k]
    {
        const int c = tid >> 2;                       // 0..63
        const int j = (c & 3) * Hsz + n0 + (c >> 2);  // W_hh row
        const float* wrow = Whh + (size_t)j * Hsz;
        for (int k = (tid & 3) * 4; k < Hsz; k += 16) {
            const float4 v = *(const float4*)(wrow + k);
            W_s[(k + 0) * 64 + c] = v.x;
            W_s[(k + 1) * 64 + c] = v.y;
            W_s[(k + 2) * 64 + c] = v.z;
            W_s[(k + 3) * 64 + c] = v.w;
        }
    }
    // ---- zero this block's slice of hbuf[0]
#pragma unroll
    for (int q = 0; q < 2; ++q) {
        const int idx = tid + q * 256;                // 0..511
        const int r = idx >> 4, cc = idx & 15;
        g_hbuf[0][(size_t)(b0 + r) * Hsz + n0 + cc] = 0.f;
    }
    grid_barrier(128);

    const int my = tid >> 4;            // 0..15 -> rows b_r0, b_r0+1
    const int nx = tid & 15;            // 0..15 -> hidden unit n
    const int b_r0 = b0 + my * 2;
    const int n    = n0 + nx;
    const bool is64 = lens_is64(lensraw);
    const int len_tile = load_len(lensraw, is64, b0);
    const int len0 = load_len(lensraw, is64, b_r0);
    const int len1 = load_len(lensraw, is64, b_r0 + 1);

    float hprev0 = 0.f, hprev1 = 0.f;   // frozen-capable h state
    float creg0  = 0.f, creg1  = 0.f;   // c state (registers)

    const float* wp = W_s + nx * 4;
    const float* hp = h_s + my * 2;

#pragma unroll 1
    for (int t = 0; t < Tsz; ++t) {
        float* hnext = g_hbuf[(t + 1) & 1];
        const bool tileActive = (t < len_tile);

        if (tileActive) {
            // -- stage h tile [32 rows][512 k] into smem (L2-coherent loads)
            {
                const float* hbuf = g_hbuf[t & 1];
                const int bloc = tid & 31;
                const int kblk = tid >> 5;
                const float* hb = hbuf + (size_t)(b0 + bloc) * Hsz + kblk * 64;
#pragma unroll
                for (int i = 0; i < 16; ++i) {
                    const float4 v = __ldcg((const float4*)(hb + i * 4));
                    const int k = kblk * 64 + i * 4;
                    h_s[(k + 0) * 32 + bloc] = v.x;
                    h_s[(k + 1) * 32 + bloc] = v.y;
                    h_s[(k + 2) * 32 + bloc] = v.z;
                    h_s[(k + 3) * 32 + bloc] = v.w;
                }
            }
            __syncthreads();

            // -- 2x4 micro-GEMM over K=512, packed f32x2
            //    pairs: A0=(g_i,g_f) row0, A1=(g_g,g_o) row0, A2/A3 row1
            unsigned long long A0 = 0ull, A1 = 0ull, A2 = 0ull, A3 = 0ull;
#pragma unroll 8
            for (int k = 0; k < Hsz; ++k) {
                const ulonglong2 wv = *(const ulonglong2*)(wp + k * 64);
                const float2 h2 = *(const float2*)(hp + k * 32);
                const unsigned long long hx = pack2(h2.x, h2.x);
                const unsigned long long hy = pack2(h2.y, h2.y);
                FMA2(A0, hx, wv.x);
                FMA2(A1, hx, wv.y);
                FMA2(A2, hy, wv.x);
                FMA2(A3, hy, wv.y);
            }
            float a0x, a0y, a0z, a0w, a1x, a1y, a1z, a1w;
            unpack2(A0, a0x, a0y); unpack2(A1, a0z, a0w);
            unpack2(A2, a1x, a1y); unpack2(A3, a1z, a1w);

            // -- elementwise LSTM update for 2 batch rows
            const float* Gt = g_G + (size_t)t * Bsz * G4;
            {
                const float* gr = Gt + (size_t)b_r0 * G4 + n;
                const float iv = sigmf(a0x + gr[0]);
                const float fv = sigmf(a0y + gr[512]);
                const float gv = tanhf(a0z + gr[1024]);
                const float ov = sigmf(a0w + gr[1536]);
                const float cn = fv * creg0 + iv * gv;
                const float hn = ov * tanhf(cn);
                const bool act = (t < len0);
                creg0  = act ? cn : creg0;
                hprev0 = act ? hn : hprev0;
                out[((size_t)b_r0 * Tsz + t) * Hsz + n] = act ? hn : 0.f;
                hnext[(size_t)b_r0 * Hsz + n] = hprev0;
            }
            {
                const float* gr = Gt + (size_t)(b_r0 + 1) * G4 + n;
                const float iv = sigmf(a1x + gr[0]);
                const float fv = sigmf(a1y + gr[512]);
                const float gv = tanhf(a1z + gr[1024]);
                const float ov = sigmf(a1w + gr[1536]);
                const float cn = fv * creg1 + iv * gv;
                const float hn = ov * tanhf(cn);
                const bool act = (t < len1);
                creg1  = act ? cn : creg1;
                hprev1 = act ? hn : hprev1;
                out[((size_t)(b_r0 + 1) * Tsz + t) * Hsz + n] = act ? hn : 0.f;
                hnext[(size_t)(b_r0 + 1) * Hsz + n] = hprev1;
            }
        } else {
            // whole batch tile inactive: zero outputs, carry h forward
            out[((size_t)b_r0 * Tsz + t) * Hsz + n]       = 0.f;
            out[((size_t)(b_r0 + 1) * Tsz + t) * Hsz + n] = 0.f;
            hnext[(size_t)b_r0 * Hsz + n]       = hprev0;
            hnext[(size_t)(b_r0 + 1) * Hsz + n] = hprev1;
        }

        grid_barrier(128);   // h double-buffer handoff for step t+1
    }

    // final (frozen) states
    hfin[(size_t)b_r0 * Hsz + n]       = hprev0;
    hfin[(size_t)(b_r0 + 1) * Hsz + n] = hprev1;
    cfin[(size_t)b_r0 * Hsz + n]       = creg0;
    cfin[(size_t)(b_r0 + 1) * Hsz + n] = creg1;
}

// ---------------------------------------------------------------------------
extern "C" void kernel_launch(void* const* d_in, const int* in_sizes, int n_in,
                              void* d_out, int out_size)
{
    (void)in_sizes; (void)n_in; (void)out_size;
    const float* seq  = (const float*)d_in[0];
    const int*   lens = (const int*)d_in[1];
    const float* Wih  = (const float*)d_in[2];
    const float* Whh  = (const float*)d_in[3];
    const float* bih  = (const float*)d_in[4];
    const float* bhh  = (const float*)d_in[5];

    float* outp = (float*)d_out;
    float* hfin = outp + (size_t)Bsz * Tsz * Hsz;
    float* cfin = hfin + (size_t)Bsz * Hsz;

    // 192 KB dynamic smem for the persistent kernel (W 128KB + h 64KB)
    cudaFuncSetAttribute(lstm_steps_kernel,
                         cudaFuncAttributeMaxDynamicSharedMemorySize, 196608);

    // Phase 1: input-gate GEMM  (16 column tiles x 1024 timesteps)
    dim3 grid1(G4 / 128, Tsz);
    pregemm_kernel<<<grid1, 256>>>(seq, Wih, bih, bhh, lens);

    // Phase 2: persistent recurrence (128 co-resident blocks, sw grid barrier)
    lstm_steps_kernel<<<128, 256, 196608>>>(Whh, lens, outp, hfin, cfin);
}

// round 7
// speedup vs baseline: 1.3684x; 1.2196x over previous
#include <cuda_runtime.h>
#include <math.h>

// ---------------------------------------------------------------------------
// Problem constants: B=128, T=1024, D=512, H=512, 4H=2048
// Inputs (metadata order):
//   0: sequence_tensor f32 [128,1024,512]
//   1: batch_lengths   int32 (JAX x64 off) or int64 [128], sorted descending
//   2: W_ih f32 [2048,512]   3: W_hh f32 [2048,512]
//   4: b_ih f32 [2048]       5: b_hh f32 [2048]
// Output: concat( out[128,1024,512], h_final[1,128,512], c_final[1,128,512] )
// ---------------------------------------------------------------------------

#define Bsz   128
#define Tsz   1024
#define Dsz   512
#define Hsz   512
#define G4    2048

// Scratch: precomputed input gates  G[t][b][j]  (1 GiB)
__device__ float g_G[(size_t)Tsz * Bsz * G4];
// Double-buffered hidden state h[b][k]
__device__ float g_hbuf[2][Bsz * Hsz];
// Per-btile barrier state (4 btiles, 128B-padded lines)
__device__ __align__(128) unsigned g_bar_cnt4[4][32];
__device__ __align__(128) unsigned g_bar_gen4[4][32];

// ---- packed fp32 helpers (FFMA2 path: PTX fma.rn.f32x2) --------------------
__device__ __forceinline__ unsigned long long pack2(float x, float y) {
    unsigned long long r;
    asm("mov.b64 %0, {%1, %2};" : "=l"(r) : "f"(x), "f"(y));
    return r;
}
__device__ __forceinline__ void unpack2(unsigned long long v, float& x, float& y) {
    asm("mov.b64 {%0, %1}, %2;" : "=f"(x), "=f"(y) : "l"(v));
}
#define FMA2(d, a, b) asm("fma.rn.f32x2 %0, %1, %2, %0;" : "+l"(d) : "l"(a), "l"(b))

// ---- scoped atomics for the software barrier --------------------------------
__device__ __forceinline__ unsigned ld_acquire_gpu(unsigned* p) {
    unsigned v;
    asm volatile("ld.acquire.gpu.u32 %0, [%1];" : "=r"(v) : "l"(p) : "memory");
    return v;
}
__device__ __forceinline__ unsigned ld_relaxed_gpu(unsigned* p) {
    unsigned v;
    asm volatile("ld.relaxed.gpu.u32 %0, [%1];" : "=r"(v) : "l"(p) : "memory");
    return v;
}
__device__ __forceinline__ unsigned atom_add_acqrel_gpu(unsigned* p, unsigned v) {
    unsigned o;
    asm volatile("atom.add.acq_rel.gpu.u32 %0, [%1], %2;"
                 : "=r"(o) : "l"(p), "r"(v) : "memory");
    return o;
}
__device__ __forceinline__ void st_release_gpu(unsigned* p, unsigned v) {
    asm volatile("st.release.gpu.u32 [%0], %1;" :: "l"(p), "r"(v) : "memory");
}
__device__ __forceinline__ void st_relaxed_gpu(unsigned* p, unsigned v) {
    asm volatile("st.relaxed.gpu.u32 [%0], %1;" :: "l"(p), "r"(v) : "memory");
}

// ---- length dtype detection (int32 vs int64) --------------------------------
__device__ __forceinline__ bool lens_is64(const int* p) {
    return (p[1] == 0 && p[3] == 0 && p[5] == 0);
}
__device__ __forceinline__ int load_len(const int* p, bool is64, int b) {
    return is64 ? p[2 * b] : p[b];
}

// ---------------------------------------------------------------------------
// Phase 1: G[t][b][j] = sum_k seq[b][t][k] * W_ih[j][k] + (b_ih[j] + b_hh[j])
// 128x128x16 SGEMM per block, FFMA2 inner product (unchanged from round 6).
// ---------------------------------------------------------------------------
__global__ void __launch_bounds__(256) pregemm_kernel(
    const float* __restrict__ seq,
    const float* __restrict__ Wih,
    const float* __restrict__ bih,
    const float* __restrict__ bhh,
    const int*   __restrict__ lensraw)
{
    __shared__ float As[16][128];
    __shared__ float Bs[16][128];

    const int t   = blockIdx.y;
    const int j0  = blockIdx.x * 128;
    const int tid = threadIdx.x;
    const int tx  = tid & 15;
    const int ty  = tid >> 4;

    const bool is64 = lens_is64(lensraw);
    const bool grpActive = (load_len(lensraw, is64, ty * 8) > t);

    unsigned long long acc2[8][4];
#pragma unroll
    for (int p = 0; p < 4; ++p) {
        const int j = j0 + tx * 8 + 2 * p;
        const unsigned long long bv =
            pack2(bih[j] + bhh[j], bih[j + 1] + bhh[j + 1]);
#pragma unroll
        for (int i = 0; i < 8; ++i) acc2[i][p] = bv;
    }

    const int lm = tid >> 1;
    const int lk = (tid & 1) * 8;
    const float* arow = seq + ((size_t)lm * Tsz + t) * Dsz + lk;
    const float* brow = Wih + (size_t)(j0 + lm) * Dsz + lk;

    for (int k0 = 0; k0 < Dsz; k0 += 16) {
        const float4 av0 = *(const float4*)(arow + k0);
        const float4 av1 = *(const float4*)(arow + k0 + 4);
        const float4 bv0 = *(const float4*)(brow + k0);
        const float4 bv1 = *(const float4*)(brow + k0 + 4);
        As[lk + 0][lm] = av0.x; As[lk + 1][lm] = av0.y;
        As[lk + 2][lm] = av0.z; As[lk + 3][lm] = av0.w;
        As[lk + 4][lm] = av1.x; As[lk + 5][lm] = av1.y;
        As[lk + 6][lm] = av1.z; As[lk + 7][lm] = av1.w;
        Bs[lk + 0][lm] = bv0.x; Bs[lk + 1][lm] = bv0.y;
        Bs[lk + 2][lm] = bv0.z; Bs[lk + 3][lm] = bv0.w;
        Bs[lk + 4][lm] = bv1.x; Bs[lk + 5][lm] = bv1.y;
        Bs[lk + 6][lm] = bv1.z; Bs[lk + 7][lm] = bv1.w;
        __syncthreads();

        if (grpActive) {
#pragma unroll
            for (int kk = 0; kk < 16; ++kk) {
                const float4 a0 = *(const float4*)&As[kk][ty * 8];
                const float4 a1 = *(const float4*)&As[kk][ty * 8 + 4];
                const ulonglong2 bb0 = *(const ulonglong2*)&Bs[kk][tx * 8];
                const ulonglong2 bb1 = *(const ulonglong2*)&Bs[kk][tx * 8 + 4];
                const float a[8] = {a0.x, a0.y, a0.z, a0.w,
                                    a1.x, a1.y, a1.z, a1.w};
#pragma unroll
                for (int i = 0; i < 8; ++i) {
                    const unsigned long long ad = pack2(a[i], a[i]);
                    FMA2(acc2[i][0], ad, bb0.x);
                    FMA2(acc2[i][1], ad, bb0.y);
                    FMA2(acc2[i][2], ad, bb1.x);
                    FMA2(acc2[i][3], ad, bb1.y);
                }
            }
        }
        __syncthreads();
    }

    if (grpActive) {
#pragma unroll
        for (int i = 0; i < 8; ++i) {
            float f0, f1, f2, f3, f4, f5, f6, f7;
            unpack2(acc2[i][0], f0, f1);
            unpack2(acc2[i][1], f2, f3);
            unpack2(acc2[i][2], f4, f5);
            unpack2(acc2[i][3], f6, f7);
            const size_t o = ((size_t)t * Bsz + ty * 8 + i) * G4 + j0 + tx * 8;
            *(float4*)&g_G[o]     = make_float4(f0, f1, f2, f3);
            *(float4*)&g_G[o + 4] = make_float4(f4, f5, f6, f7);
        }
    }
}

// ---------------------------------------------------------------------------
// Per-btile software barrier (32 blocks).  Release/acquire atomics only —
// no MEMBAR storm.  bar.sync gives intra-block hb; thread0's acq_rel arrive
// publishes all block stores; waiters acquire on the generation flag; the
// releaser (last arriver) gets acquire from its own acq_rel add.
// Sense-reversing, replay-safe (cnt ends 0, gen monotonic across launches).
// All cross-step global reads use __ldcg (L2-coherent).
// ---------------------------------------------------------------------------
__device__ __forceinline__ void tile_barrier(unsigned* cnt, unsigned* gen)
{
    __syncthreads();
    if (threadIdx.x == 0) {
        const unsigned old = ld_relaxed_gpu(gen);     // before arrive (rel order)
        const unsigned ticket = atom_add_acqrel_gpu(cnt, 1u);
        if (ticket == 31u) {
            st_relaxed_gpu(cnt, 0u);                  // ordered by release below
            st_release_gpu(gen, old + 1u);
        } else {
            while (ld_acquire_gpu(gen) == old) { }
        }
    }
    __syncthreads();
}

__device__ __forceinline__ float sigmf(float x) {
    return __fdividef(1.f, 1.f + __expf(-x));
}
__device__ __forceinline__ float tanh_fast(float x) {
    return 1.f - __fdividef(2.f, __expf(2.f * x) + 1.f);
}

// ---------------------------------------------------------------------------
// Phase 2: persistent recurrence kernel.
// 128 blocks = (btile 0..3 [32 batch rows]) x (ntile 0..31 [16 hidden]).
// Tile column c = 4*n_off + gate.  W_hh tile (64x512, 128KB) in smem once;
// h staged per step via __ldcg; c in registers; per-btile barrier;
// G prefetched at step start; out zero-filled up front.
// ---------------------------------------------------------------------------
__global__ void __launch_bounds__(256, 1) lstm_steps_kernel(
    const float* __restrict__ Whh,
    const int*   __restrict__ lensraw,
    float* __restrict__ out,    // [B,T,H]
    float* __restrict__ hfin,   // [B,H]
    float* __restrict__ cfin)   // [B,H]
{
    extern __shared__ float sm[];
    float* W_s = sm;                 // [512][64]  W_s[k][c]
    float* h_s = sm + 512 * 64;      // [512][32]  h_s[k][b_local]

    const int tid   = threadIdx.x;
    const int bx    = blockIdx.x;        // 0..127
    const int ntile = bx & 31;
    const int btile = bx >> 5;
    const int n0    = ntile * 16;
    const int b0    = btile * 32;
    unsigned* bar_cnt = &g_bar_cnt4[btile][0];
    unsigned* bar_gen = &g_bar_gen4[btile][0];

    // ---- stage W_hh tile (once): W_s[k][c] = Whh[(c&3)*512 + n0 + (c>>2)][k]
    {
        const int c = tid >> 2;                       // 0..63
        const int j = (c & 3) * Hsz + n0 + (c >> 2);
        const float* wrow = Whh + (size_t)j * Hsz;
        for (int k = (tid & 3) * 4; k < Hsz; k += 16) {
            const float4 v = *(const float4*)(wrow + k);
            W_s[(k + 0) * 64 + c] = v.x;
            W_s[(k + 1) * 64 + c] = v.y;
            W_s[(k + 2) * 64 + c] = v.z;
            W_s[(k + 3) * 64 + c] = v.w;
        }
    }
    // ---- zero this block's slice of hbuf[0]
#pragma unroll
    for (int q = 0; q < 2; ++q) {
        const int idx = tid + q * 256;
        const int r = idx >> 4, cc = idx & 15;
        g_hbuf[0][(size_t)(b0 + r) * Hsz + n0 + cc] = 0.f;
    }
    // ---- zero-fill out for this btile: rows [b0,b0+32), t in [ntile*32,+32)
    {
        const float4 z4 = make_float4(0.f, 0.f, 0.f, 0.f);
        for (int it = 0; it < 512; ++it) {
            const int p  = it * 2 + (tid >> 7);       // (b,t) pair 0..1023
            const int r  = p >> 5;
            const int tt = ntile * 32 + (p & 31);
            float4* dst = (float4*)(out + ((size_t)(b0 + r) * Tsz + tt) * Hsz);
            dst[tid & 127] = z4;
        }
    }
    tile_barrier(bar_cnt, bar_gen);

    const int my = tid >> 4;            // 0..15 -> rows b_r0, b_r0+1
    const int nx = tid & 15;            // 0..15 -> hidden unit n
    const int b_r0 = b0 + my * 2;
    const int n    = n0 + nx;
    const bool is64 = lens_is64(lensraw);
    const int len_tile = load_len(lensraw, is64, b0);
    const int len0 = load_len(lensraw, is64, b_r0);
    const int len1 = load_len(lensraw, is64, b_r0 + 1);

    float hprev0 = 0.f, hprev1 = 0.f;
    float creg0  = 0.f, creg1  = 0.f;

    const float* wp = W_s + nx * 4;
    const float* hp = h_s + my * 2;

#pragma unroll 1
    for (int t = 0; t < Tsz; ++t) {
        float* hnext = g_hbuf[(t + 1) & 1];
        const bool tileActive = (t < len_tile);

        if (tileActive) {
            // -- prefetch G[t] (DRAM, independent of h) early
            const float* gr0 = g_G + ((size_t)t * Bsz + b_r0) * G4 + n;
            const float gi0 = __ldcg(gr0);
            const float gf0 = __ldcg(gr0 + 512);
            const float gg0 = __ldcg(gr0 + 1024);
            const float go0 = __ldcg(gr0 + 1536);
            const float gi1 = __ldcg(gr0 + G4);
            const float gf1 = __ldcg(gr0 + G4 + 512);
            const float gg1 = __ldcg(gr0 + G4 + 1024);
            const float go1 = __ldcg(gr0 + G4 + 1536);

            // -- stage h tile [32 rows][512 k] into smem (L2-coherent loads)
            {
                const float* hbuf = g_hbuf[t & 1];
                const int bloc = tid & 31;
                const int kblk = tid >> 5;
                const float* hb = hbuf + (size_t)(b0 + bloc) * Hsz + kblk * 64;
#pragma unroll
                for (int i = 0; i < 16; ++i) {
                    const float4 v = __ldcg((const float4*)(hb + i * 4));
                    const int k = kblk * 64 + i * 4;
                    h_s[(k + 0) * 32 + bloc] = v.x;
                    h_s[(k + 1) * 32 + bloc] = v.y;
                    h_s[(k + 2) * 32 + bloc] = v.z;
                    h_s[(k + 3) * 32 + bloc] = v.w;
                }
            }
            __syncthreads();

            // -- 2x4 micro-GEMM over K=512, packed f32x2, deep unroll
            unsigned long long A0 = 0ull, A1 = 0ull, A2 = 0ull, A3 = 0ull;
#pragma unroll 16
            for (int k = 0; k < Hsz; ++k) {
                const ulonglong2 wv = *(const ulonglong2*)(wp + k * 64);
                const float2 h2 = *(const float2*)(hp + k * 32);
                const unsigned long long hx = pack2(h2.x, h2.x);
                const unsigned long long hy = pack2(h2.y, h2.y);
                FMA2(A0, hx, wv.x);
                FMA2(A1, hx, wv.y);
                FMA2(A2, hy, wv.x);
                FMA2(A3, hy, wv.y);
            }
            float a0x, a0y, a0z, a0w, a1x, a1y, a1z, a1w;
            unpack2(A0, a0x, a0y); unpack2(A1, a0z, a0w);
            unpack2(A2, a1x, a1y); unpack2(A3, a1z, a1w);

            // -- elementwise LSTM update for 2 batch rows
            {
                const float iv = sigmf(a0x + gi0);
                const float fv = sigmf(a0y + gf0);
                const float gv = tanh_fast(a0z + gg0);
                const float ov = sigmf(a0w + go0);
                const float cn = fv * creg0 + iv * gv;
                const float hn = ov * tanh_fast(cn);
                const bool act = (t < len0);
                creg0  = act ? cn : creg0;
                hprev0 = act ? hn : hprev0;
                if (act) out[((size_t)b_r0 * Tsz + t) * Hsz + n] = hn;
                hnext[(size_t)b_r0 * Hsz + n] = hprev0;
            }
            {
                const float iv = sigmf(a1x + gi1);
                const float fv = sigmf(a1y + gf1);
                const float gv = tanh_fast(a1z + gg1);
                const float ov = sigmf(a1w + go1);
                const float cn = fv * creg1 + iv * gv;
                const float hn = ov * tanh_fast(cn);
                const bool act = (t < len1);
                creg1  = act ? cn : creg1;
                hprev1 = act ? hn : hprev1;
                if (act) out[((size_t)(b_r0 + 1) * Tsz + t) * Hsz + n] = hn;
                hnext[(size_t)(b_r0 + 1) * Hsz + n] = hprev1;
            }
        }
        // inactive tile: outputs already zero-filled, h frozen, nothing to do

        tile_barrier(bar_cnt, bar_gen);   // h handoff within this btile
    }

    // final (frozen) states
    hfin[(size_t)b_r0 * Hsz + n]       = hprev0;
    hfin[(size_t)(b_r0 + 1) * Hsz + n] = hprev1;
    cfin[(size_t)b_r0 * Hsz + n]       = creg0;
    cfin[(size_t)(b_r0 + 1) * Hsz + n] = creg1;
}

// ---------------------------------------------------------------------------
extern "C" void kernel_launch(void* const* d_in, const int* in_sizes, int n_in,
                              void* d_out, int out_size)
{
    (void)in_sizes; (void)n_in; (void)out_size;
    const float* seq  = (const float*)d_in[0];
    const int*   lens = (const int*)d_in[1];
    const float* Wih  = (const float*)d_in[2];
    const float* Whh  = (const float*)d_in[3];
    const float* bih  = (const float*)d_in[4];
    const float* bhh  = (const float*)d_in[5];

    float* outp = (float*)d_out;
    float* hfin = outp + (size_t)Bsz * Tsz * Hsz;
    float* cfin = hfin + (size_t)Bsz * Hsz;

    // 192 KB dynamic smem for the persistent kernel (W 128KB + h 64KB)
    cudaFuncSetAttribute(lstm_steps_kernel,
                         cudaFuncAttributeMaxDynamicSharedMemorySize, 196608);

    // Phase 1: input-gate GEMM  (16 column tiles x 1024 timesteps)
    dim3 grid1(G4 / 128, Tsz);
    pregemm_kernel<<<grid1, 256>>>(seq, Wih, bih, bhh, lens);

    // Phase 2: persistent recurrence (128 co-resident blocks, btile barriers)
    lstm_steps_kernel<<<128, 256, 196608>>>(Whh, lens, outp, hfin, cfin);
}